// round 14
// baseline (speedup 1.0000x reference)
#include <cuda_runtime.h>

// Problem constants
#define BB 256
#define TT 1024
#define VV 6
#define DD 64
#define UU 64
#define GG 256   // 4*U gate columns

// Precomputed per-vocab tables (V=6).
// Forward table PERMUTED for the 2-col/thread mapping: thread l (u=l>>1,
// p=l&1) owns cols {p*64+u, 128+p*64+u} and reads slots {2l, 2l+1} as LDS.64.
// Original col g (gi=g>>6, u=g&63) -> slot 4u + 2*(gi&1) + (gi>>1).
__device__ float g_xprojF[VV][GG];
__device__ float g_xprojB[VV][GG];   // unpermuted (epilogue indexes by gate)
__device__ int   g_maskv[VV];

__device__ __forceinline__ float sigmoid_fast(float x) {
    return __fdividef(1.f, 1.f + __expf(-x));
}
__device__ __forceinline__ float tanh_fast(float x) {
    return 2.f * __fdividef(1.f, 1.f + __expf(-2.f * x)) - 1.f;
}

__device__ __forceinline__ unsigned long long pack2(float lo, float hi) {
    unsigned long long r;
    asm("mov.b64 %0, {%1, %2};" : "=l"(r) : "f"(lo), "f"(hi));
    return r;
}
__device__ __forceinline__ void unpack2(unsigned long long v, float& lo, float& hi) {
    asm("mov.b64 {%0, %1}, %2;" : "=f"(lo), "=f"(hi) : "l"(v));
}
// Packed dual-FMA: lanes {lo,hi} independently (sm_10x FFMA2 path)
#define FMA2(d, a, b, c) \
    asm("fma.rn.f32x2 %0, %1, %2, %3;" : "=l"(d) : "l"(a), "l"(b), "l"(c))
#define ADD2(d, a, b) \
    asm("add.rn.f32x2 %0, %1, %2;" : "=l"(d) : "l"(a), "l"(b))

__global__ void precompute_kernel(const float* __restrict__ emb,
                                  const float* __restrict__ Wk_f,
                                  const float* __restrict__ b_f,
                                  const float* __restrict__ Wk_b,
                                  const float* __restrict__ b_b) {
    int v = blockIdx.x;
    int g = threadIdx.x;          // original gate column
    float sf = 0.f, sb = 0.f;
    #pragma unroll 8
    for (int k = 0; k < DD; k++) {
        float e = emb[v * DD + k];
        sf = fmaf(e, Wk_f[k * GG + g], sf);
        sb = fmaf(e, Wk_b[k * GG + g], sb);
    }
    int u = g & 63, gi = g >> 6;
    int slot = 4 * u + 2 * (gi & 1) + (gi >> 1);
    g_xprojF[v][slot] = sf + b_f[g];
    g_xprojB[v][g]    = sb + b_b[g];
    if (g == 0) {
        int m = 0;
        for (int k = 0; k < DD; k++) m |= (emb[v * DD + k] != 0.f);
        g_maskv[v] = m;
    }
}

// BURST: one batch's matvec for one step. Seeds folded into acc init;
// produces two reduced b64 accumulators (colA, colB). 64 FMA2 + 16 LDS.128.
__device__ __forceinline__ void burst(
    const float* __restrict__ hr,
    const unsigned long long* __restrict__ wA,
    const unsigned long long* __restrict__ wB,
    float2 seed, unsigned long long& accA, unsigned long long& accB)
{
    unsigned long long A0 = pack2(seed.x, 0.f), A1 = 0ull;
    unsigned long long B0 = pack2(seed.y, 0.f), B1 = 0ull;
    const ulonglong2* __restrict__ hp = (const ulonglong2*)hr;
    #pragma unroll
    for (int i = 0; i < 16; i += 2) {
        ulonglong2 pX = hp[i];       // {h4i,h4i+1},{h4i+2,h4i+3}
        ulonglong2 pY = hp[i + 1];
        FMA2(A0, pX.x, wA[2 * i + 0], A0);
        FMA2(B0, pX.x, wB[2 * i + 0], B0);
        FMA2(A1, pX.y, wA[2 * i + 1], A1);
        FMA2(B1, pX.y, wB[2 * i + 1], B1);
        FMA2(A0, pY.x, wA[2 * i + 2], A0);
        FMA2(B0, pY.x, wB[2 * i + 2], B0);
        FMA2(A1, pY.y, wA[2 * i + 3], A1);
        FMA2(B1, pY.y, wB[2 * i + 3], B1);
    }
    ADD2(A0, A0, A1);
    ADD2(B0, B0, B1);
    accA = A0;
    accB = B0;
}

// TAIL: finish one batch's step from carried accumulators: activations,
// quad-free A->B exchange (one shfl), c/h update, h store.
__device__ __forceinline__ void tail(
    unsigned long long accA, unsigned long long accB,
    int m, int p, int u, float& c, float& hprev, float* __restrict__ hw)
{
    float lo, hi;
    unpack2(accA, lo, hi); float zA = lo + hi;   // i (p=0) or f (p=1)
    unpack2(accB, lo, hi); float zB = lo + hi;   // g (p=0) or o (p=1)
    float aA = sigmoid_fast(zA);
    float aB = (p == 0) ? tanh_fast(zB) : sigmoid_fast(zB);
    float ig = __shfl_xor_sync(0xffffffffu, aA * aB, 1);  // A->B: i*g
    if (p == 1) {
        float cn = fmaf(aA, c, ig);          // f*c + i*g
        float hn = aB * tanh_fast(cn);       // o * tanh(c)
        c     = m ? cn : c;
        hprev = m ? hn : hprev;
        hw[u] = hprev;
    }
}

// Grid 128 CTAs x 128 threads: 1 CTA/SM, 4 warps/SM = one warp per SMSP.
// Each thread runs its 2 gate columns for BOTH of the CTA's batches, but the
// batches are SKEWED by half a step: in program order each batch's tail is
// followed by the OTHER batch's independent FMA burst, so the scheduler
// hides the MUFU/shuffle tail under the burst. Accumulators carry across
// the barrier in registers. Two barriers per time-step, one per h-publish.
__global__ void __launch_bounds__(128, 1)
lstm_fwd_kernel(const int* __restrict__ tokens,
                const float* __restrict__ Wr_f,
                const float* __restrict__ Wd,
                const float* __restrict__ bd,
                float* __restrict__ out) {
    __shared__ float sh_xF[VV * GG];                 // 6 KB (permuted)
    __shared__ int   sh_tok[2][TT + 2];              // pad for pipeline tail
    __shared__ __align__(16) float sh_h[2][2][UU];   // [batch][parity][unit]
    __shared__ int   sh_mask[VV];
    __shared__ float sh_red[2][2];

    const int l    = threadIdx.x;        // 0..127
    const int b0   = blockIdx.x * 2;
    const int b1   = b0 + 1;
    const int u    = l >> 1;
    const int p    = l & 1;              // 0 = A{i,g}, 1 = B{f,o}
    const int colA = p * UU + u;         // i or f
    const int colB = 2 * UU + p * UU + u;// g or o
    const int lane = l & 31;

    // Recurrent weight columns as k-pairs (register-resident, shared by both batches).
    unsigned long long wA[32], wB[32];
    #pragma unroll
    for (int j = 0; j < 32; j++) {
        wA[j] = pack2(Wr_f[(2 * j) * GG + colA], Wr_f[(2 * j + 1) * GG + colA]);
        wB[j] = pack2(Wr_f[(2 * j) * GG + colB], Wr_f[(2 * j + 1) * GG + colB]);
    }

    // Stage tokens (both batches) and tables.
    for (int i = l; i < TT; i += 128) {
        sh_tok[0][i] = tokens[b0 * TT + i];
        sh_tok[1][i] = tokens[b1 * TT + i];
    }
    if (l == 0) { sh_tok[0][TT] = 0; sh_tok[0][TT + 1] = 0;
                  sh_tok[1][TT] = 0; sh_tok[1][TT + 1] = 0; }
    for (int i = l; i < VV * GG; i += 128) sh_xF[i] = (&g_xprojF[0][0])[i];
    if (l < VV) sh_mask[l] = g_maskv[l];
    if (l < UU) {
        sh_h[0][0][l] = 0.f; sh_h[0][1][l] = 0.f;
        sh_h[1][0][l] = 0.f; sh_h[1][1][l] = 0.f;
    }
    __syncthreads();

    float c0 = 0.f, hp0 = 0.f;   // batch0 state (B threads)
    float c1 = 0.f, hp1 = 0.f;   // batch1

    float* __restrict__ h0A = sh_h[0][0];   // b0 parity0
    float* __restrict__ h0B = sh_h[0][1];   // b0 parity1
    float* __restrict__ h1A = sh_h[1][0];   // b1 parity0
    float* __restrict__ h1B = sh_h[1][1];   // b1 parity1

    unsigned long long a0A, a0B, a1A, a1B;  // carried accumulators

    // Pipeline prologue: b0 step0 burst (h0A is zeros); prefetch b1 step0.
    int    tok0 = sh_tok[0][0];
    float2 sd0  = *(const float2*)&sh_xF[tok0 * GG + 2 * l];
    int    m0   = sh_mask[tok0];
    burst(h0A, wA, wB, sd0, a0A, a0B);

    int    tok1 = sh_tok[1][0];
    float2 sd1  = *(const float2*)&sh_xF[tok1 * GG + 2 * l];
    int    m1   = sh_mask[tok1];

    for (int s = 0; s < TT; s += 2) {
        // phase A (step s): tail b0 -> h0B ; burst b1(s) reads h1A
        tail(a0A, a0B, m0, p, u, c0, hp0, h0B);
        burst(h1A, wA, wB, sd1, a1A, a1B);
        tok0 = sh_tok[0][s + 1];
        sd0  = *(const float2*)&sh_xF[tok0 * GG + 2 * l];
        m0   = sh_mask[tok0];
        __syncthreads();                       // publish h0B

        // phase B: tail b1 -> h1B ; burst b0(s+1) reads h0B
        tail(a1A, a1B, m1, p, u, c1, hp1, h1B);
        burst(h0B, wA, wB, sd0, a0A, a0B);
        tok1 = sh_tok[1][s + 1];
        sd1  = *(const float2*)&sh_xF[tok1 * GG + 2 * l];
        m1   = sh_mask[tok1];
        __syncthreads();                       // publish h1B

        // phase C (step s+1): tail b0 -> h0A ; burst b1(s+1) reads h1B
        tail(a0A, a0B, m0, p, u, c0, hp0, h0A);
        burst(h1B, wA, wB, sd1, a1A, a1B);
        tok0 = sh_tok[0][s + 2];
        sd0  = *(const float2*)&sh_xF[tok0 * GG + 2 * l];
        m0   = sh_mask[tok0];
        __syncthreads();                       // publish h0A

        // phase D: tail b1 -> h1A ; burst b0(s+2) reads h0A
        // (last iteration: burst for step TT is harmless — pad token, accs dropped)
        tail(a1A, a1B, m1, p, u, c1, hp1, h1A);
        burst(h0A, wA, wB, sd0, a0A, a0B);
        tok1 = sh_tok[1][s + 2];
        sd1  = *(const float2*)&sh_xF[tok1 * GG + 2 * l];
        m1   = sh_mask[tok1];
        __syncthreads();                       // publish h1A
    }

    // Final forward h for both batches is in parity 0 (step 1023 wrote it).
    // Backward direction = its first step only (h0=c0=0): z = xprojB(x[T-1]),
    // c = i*g, h_b = o*tanh(c), masked -> 0.
    if (l < UU) {
        const int tL0 = sh_tok[0][TT - 1];
        const int tL1 = sh_tok[1][TT - 1];

        float ii0 = sigmoid_fast(g_xprojB[tL0][l]);
        float gg0 = tanh_fast  (g_xprojB[tL0][2 * UU + l]);
        float oo0 = sigmoid_fast(g_xprojB[tL0][3 * UU + l]);
        float hb0 = sh_mask[tL0] ? oo0 * tanh_fast(ii0 * gg0) : 0.f;

        float ii1 = sigmoid_fast(g_xprojB[tL1][l]);
        float gg1 = tanh_fast  (g_xprojB[tL1][2 * UU + l]);
        float oo1 = sigmoid_fast(g_xprojB[tL1][3 * UU + l]);
        float hb1 = sh_mask[tL1] ? oo1 * tanh_fast(ii1 * gg1) : 0.f;

        float ct0 = sh_h[0][0][l] * Wd[l] + hb0 * Wd[UU + l];
        float ct1 = sh_h[1][0][l] * Wd[l] + hb1 * Wd[UU + l];
        #pragma unroll
        for (int off = 16; off > 0; off >>= 1) {
            ct0 += __shfl_down_sync(0xffffffffu, ct0, off);
            ct1 += __shfl_down_sync(0xffffffffu, ct1, off);
        }
        if (lane == 0) {
            sh_red[0][l >> 5] = ct0;    // warps 0,1 hold l<64
            sh_red[1][l >> 5] = ct1;
        }
    }
    __syncthreads();
    if (l == 0) {
        out[b0] = sh_red[0][0] + sh_red[0][1] + bd[0];
        out[b1] = sh_red[1][0] + sh_red[1][1] + bd[0];
    }
}

// Input order (metadata): tokens, emb, Wk_f, Wr_f, b_f, Wk_b, Wr_b, b_b, Wd, bd
extern "C" void kernel_launch(void* const* d_in, const int* in_sizes, int n_in,
                              void* d_out, int out_size) {
    const int*   tokens = (const int*)  d_in[0];
    const float* emb    = (const float*)d_in[1];
    const float* Wk_f   = (const float*)d_in[2];
    const float* Wr_f   = (const float*)d_in[3];
    const float* b_f    = (const float*)d_in[4];
    const float* Wk_b   = (const float*)d_in[5];
    // d_in[6] = Wr_b: unused (backward recurrence collapses to step 1 from h0=0)
    const float* b_b    = (const float*)d_in[7];
    const float* Wd     = (const float*)d_in[8];
    const float* bd     = (const float*)d_in[9];
    float*       out    = (float*)d_out;

    precompute_kernel<<<VV, GG>>>(emb, Wk_f, b_f, Wk_b, b_b);
    lstm_fwd_kernel<<<BB / 2, 128>>>(tokens, Wr_f, Wd, bd, out);
}

// round 15
// speedup vs baseline: 2.2156x; 2.2156x over previous
#include <cuda_runtime.h>

// Problem constants
#define BB 256
#define TT 1024
#define VV 6
#define DD 64
#define UU 64
#define GG 256   // 4*U gate columns

// Precomputed per-vocab tables (V=6).
// Forward table PERMUTED for the 2-col/thread mapping: thread l (u=l>>1,
// p=l&1) owns cols {p*64+u, 128+p*64+u} and reads slots {2l, 2l+1} as LDS.64.
// Original col g (gi=g>>6, u=g&63) -> slot 4u + 2*(gi&1) + (gi>>1).
__device__ float g_xprojF[VV][GG];
__device__ float g_xprojB[VV][GG];   // unpermuted (epilogue indexes by gate)
__device__ int   g_maskv[VV];

__device__ __forceinline__ float sigmoid_fast(float x) {
    return __fdividef(1.f, 1.f + __expf(-x));
}
__device__ __forceinline__ float tanh_fast(float x) {
    return 2.f * __fdividef(1.f, 1.f + __expf(-2.f * x)) - 1.f;
}

__device__ __forceinline__ unsigned long long pack2(float lo, float hi) {
    unsigned long long r;
    asm("mov.b64 %0, {%1, %2};" : "=l"(r) : "f"(lo), "f"(hi));
    return r;
}
__device__ __forceinline__ void unpack2(unsigned long long v, float& lo, float& hi) {
    asm("mov.b64 {%0, %1}, %2;" : "=f"(lo), "=f"(hi) : "l"(v));
}
// Packed dual-FMA: lanes {lo,hi} independently (sm_10x FFMA2 path)
#define FMA2(d, a, b, c) \
    asm("fma.rn.f32x2 %0, %1, %2, %3;" : "=l"(d) : "l"(a), "l"(b), "l"(c))
#define ADD2(d, a, b) \
    asm("add.rn.f32x2 %0, %1, %2;" : "=l"(d) : "l"(a), "l"(b))

__global__ void precompute_kernel(const float* __restrict__ emb,
                                  const float* __restrict__ Wk_f,
                                  const float* __restrict__ b_f,
                                  const float* __restrict__ Wk_b,
                                  const float* __restrict__ b_b) {
    int v = blockIdx.x;
    int g = threadIdx.x;          // original gate column
    float sf = 0.f, sb = 0.f;
    #pragma unroll 8
    for (int k = 0; k < DD; k++) {
        float e = emb[v * DD + k];
        sf = fmaf(e, Wk_f[k * GG + g], sf);
        sb = fmaf(e, Wk_b[k * GG + g], sb);
    }
    int u = g & 63, gi = g >> 6;
    int slot = 4 * u + 2 * (gi & 1) + (gi >> 1);
    g_xprojF[v][slot] = sf + b_f[g];
    g_xprojB[v][g]    = sb + b_b[g];
    if (g == 0) {
        int m = 0;
        for (int k = 0; k < DD; k++) m |= (emb[v * DD + k] != 0.f);
        g_maskv[v] = m;
    }
}

// FUSED step, 4-way split accumulator chains (depth 8 instead of 32).
// Both batches advance one time-step in ONE statement-interleaved stream.
// k-pair j feeds chain j&3, so consecutive FMA2s on the same chain are
// separated by ~32 independent instructions — the dependent-chain latency
// (suspected ~12 cyc for the paired FFMA2 op) is fully pipelined.
__device__ __forceinline__ void lstm_step2(
    const float* __restrict__ hr0, float* __restrict__ hw0,
    const float* __restrict__ hr1, float* __restrict__ hw1,
    const unsigned long long* __restrict__ wA,
    const unsigned long long* __restrict__ wB,
    float2 sd0, float2 sd1, int m0, int m1, int p, int u,
    float& c0, float& hp0, float& c1, float& hp1)
{
    // 16 accumulators: [batch][col][chain 0..3]; seeds folded into chain 0.
    unsigned long long A0[4], B0[4], A1[4], B1[4];
    A0[0] = pack2(sd0.x, 0.f); A0[1] = 0ull; A0[2] = 0ull; A0[3] = 0ull;
    B0[0] = pack2(sd0.y, 0.f); B0[1] = 0ull; B0[2] = 0ull; B0[3] = 0ull;
    A1[0] = pack2(sd1.x, 0.f); A1[1] = 0ull; A1[2] = 0ull; A1[3] = 0ull;
    B1[0] = pack2(sd1.y, 0.f); B1[1] = 0ull; B1[2] = 0ull; B1[3] = 0ull;
    const ulonglong2* __restrict__ h0p = (const ulonglong2*)hr0;
    const ulonglong2* __restrict__ h1p = (const ulonglong2*)hr1;
    #pragma unroll
    for (int i = 0; i < 16; i++) {
        ulonglong2 x0 = h0p[i];          // b0 h k-pairs {2i, 2i+1}
        ulonglong2 x1 = h1p[i];          // b1
        const int ce = (2 * i) & 3;      // chain for even pair (0 or 2)
        const int co = (2 * i + 1) & 3;  // chain for odd pair  (1 or 3)
        FMA2(A0[ce], x0.x, wA[2 * i + 0], A0[ce]);
        FMA2(A1[ce], x1.x, wA[2 * i + 0], A1[ce]);
        FMA2(B0[ce], x0.x, wB[2 * i + 0], B0[ce]);
        FMA2(B1[ce], x1.x, wB[2 * i + 0], B1[ce]);
        FMA2(A0[co], x0.y, wA[2 * i + 1], A0[co]);
        FMA2(A1[co], x1.y, wA[2 * i + 1], A1[co]);
        FMA2(B0[co], x0.y, wB[2 * i + 1], B0[co]);
        FMA2(B1[co], x1.y, wB[2 * i + 1], B1[co]);
    }
    // Depth-2 reduction trees, interleaved across the 4 col/batch groups.
    ADD2(A0[0], A0[0], A0[1]); ADD2(A0[2], A0[2], A0[3]);
    ADD2(A1[0], A1[0], A1[1]); ADD2(A1[2], A1[2], A1[3]);
    ADD2(B0[0], B0[0], B0[1]); ADD2(B0[2], B0[2], B0[3]);
    ADD2(B1[0], B1[0], B1[1]); ADD2(B1[2], B1[2], B1[3]);
    ADD2(A0[0], A0[0], A0[2]);
    ADD2(A1[0], A1[0], A1[2]);
    ADD2(B0[0], B0[0], B0[2]);
    ADD2(B1[0], B1[0], B1[2]);
    float lo, hi, zA0, zB0, zA1, zB1;
    unpack2(A0[0], lo, hi); zA0 = lo + hi;   // b0: i or f
    unpack2(A1[0], lo, hi); zA1 = lo + hi;   // b1
    unpack2(B0[0], lo, hi); zB0 = lo + hi;   // b0: g or o
    unpack2(B1[0], lo, hi); zB1 = lo + hi;   // b1
    // Activations interleaved: b0 and b1 MUFU chains overlap.
    float aA0 = sigmoid_fast(zA0);
    float aA1 = sigmoid_fast(zA1);
    float aB0 = (p == 0) ? tanh_fast(zB0) : sigmoid_fast(zB0);
    float aB1 = (p == 0) ? tanh_fast(zB1) : sigmoid_fast(zB1);
    float ig0 = __shfl_xor_sync(0xffffffffu, aA0 * aB0, 1);  // A->B: i*g
    float ig1 = __shfl_xor_sync(0xffffffffu, aA1 * aB1, 1);
    if (p == 1) {
        float cn0 = fmaf(aA0, c0, ig0);      // f*c + i*g
        float cn1 = fmaf(aA1, c1, ig1);
        float hn0 = aB0 * tanh_fast(cn0);    // o * tanh(c)
        float hn1 = aB1 * tanh_fast(cn1);
        c0  = m0 ? cn0 : c0;
        c1  = m1 ? cn1 : c1;
        hp0 = m0 ? hn0 : hp0;
        hp1 = m1 ? hn1 : hp1;
        hw0[u] = hp0;
        hw1[u] = hp1;
    }
}

// Grid 128 CTAs x 128 threads: 1 CTA/SM (single uniform wave), 4 warps/SM =
// ONE warp per SMSP. Each thread runs its 2 gate columns for BOTH of the
// CTA's batches inside one fused, statement-interleaved stream (weights
// shared). One __syncthreads per time-step covers both batches.
// Wall time == 1024 x per-step critical path, so everything targets chain
// latency, not throughput.
__global__ void __launch_bounds__(128, 1)
lstm_fwd_kernel(const int* __restrict__ tokens,
                const float* __restrict__ Wr_f,
                const float* __restrict__ Wd,
                const float* __restrict__ bd,
                float* __restrict__ out) {
    __shared__ float sh_xF[VV * GG];                 // 6 KB (permuted)
    __shared__ int   sh_tok[2][TT + 2];              // pad for prefetch
    __shared__ __align__(16) float sh_h[2][2][UU];   // [batch][parity][unit]
    __shared__ int   sh_mask[VV];
    __shared__ float sh_red[2][2];

    const int l    = threadIdx.x;        // 0..127
    const int b0   = blockIdx.x * 2;
    const int b1   = b0 + 1;
    const int u    = l >> 1;
    const int p    = l & 1;              // 0 = A{i,g}, 1 = B{f,o}
    const int colA = p * UU + u;         // i or f
    const int colB = 2 * UU + p * UU + u;// g or o
    const int lane = l & 31;

    // Recurrent weight columns as k-pairs (register-resident, shared by both batches).
    unsigned long long wA[32], wB[32];
    #pragma unroll
    for (int j = 0; j < 32; j++) {
        wA[j] = pack2(Wr_f[(2 * j) * GG + colA], Wr_f[(2 * j + 1) * GG + colA]);
        wB[j] = pack2(Wr_f[(2 * j) * GG + colB], Wr_f[(2 * j + 1) * GG + colB]);
    }

    // Stage tokens (both batches) and tables.
    for (int i = l; i < TT; i += 128) {
        sh_tok[0][i] = tokens[b0 * TT + i];
        sh_tok[1][i] = tokens[b1 * TT + i];
    }
    if (l == 0) { sh_tok[0][TT] = 0; sh_tok[0][TT + 1] = 0;
                  sh_tok[1][TT] = 0; sh_tok[1][TT + 1] = 0; }
    for (int i = l; i < VV * GG; i += 128) sh_xF[i] = (&g_xprojF[0][0])[i];
    if (l < VV) sh_mask[l] = g_maskv[l];
    if (l < UU) {
        sh_h[0][0][l] = 0.f; sh_h[0][1][l] = 0.f;
        sh_h[1][0][l] = 0.f; sh_h[1][1][l] = 0.f;
    }
    __syncthreads();

    float c0 = 0.f, hp0 = 0.f;   // batch0 cell/hidden state (B threads)
    float c1 = 0.f, hp1 = 0.f;   // batch1

    // First-step prefetch (tables are init-constant).
    int    tok0 = sh_tok[0][0];
    int    tok1 = sh_tok[1][0];
    float2 sd0  = *(const float2*)&sh_xF[tok0 * GG + 2 * l];
    float2 sd1  = *(const float2*)&sh_xF[tok1 * GG + 2 * l];
    int    m0   = sh_mask[tok0];
    int    m1   = sh_mask[tok1];

    float* __restrict__ h0A = sh_h[0][0];
    float* __restrict__ h0B = sh_h[0][1];
    float* __restrict__ h1A = sh_h[1][0];
    float* __restrict__ h1B = sh_h[1][1];

    for (int s = 0; s < TT; s += 2) {
        // --- even step: read parity0, write parity1 (both batches, fused) ---
        lstm_step2(h0A, h0B, h1A, h1B, wA, wB, sd0, sd1, m0, m1, p, u,
                   c0, hp0, c1, hp1);
        tok0 = sh_tok[0][s + 1];
        tok1 = sh_tok[1][s + 1];
        sd0  = *(const float2*)&sh_xF[tok0 * GG + 2 * l];
        sd1  = *(const float2*)&sh_xF[tok1 * GG + 2 * l];
        m0   = sh_mask[tok0];
        m1   = sh_mask[tok1];
        __syncthreads();
        // --- odd step: read parity1, write parity0 ---
        lstm_step2(h0B, h0A, h1B, h1A, wA, wB, sd0, sd1, m0, m1, p, u,
                   c0, hp0, c1, hp1);
        tok0 = sh_tok[0][s + 2];
        tok1 = sh_tok[1][s + 2];
        sd0  = *(const float2*)&sh_xF[tok0 * GG + 2 * l];
        sd1  = *(const float2*)&sh_xF[tok1 * GG + 2 * l];
        m0   = sh_mask[tok0];
        m1   = sh_mask[tok1];
        __syncthreads();
    }

    // Final forward h is in parity 0 (step 1023 wrote it).
    // Backward direction = its first step only (h0=c0=0): z = xprojB(x[T-1]),
    // c = i*g, h_b = o*tanh(c), masked -> 0.
    if (l < UU) {
        const int tL0 = sh_tok[0][TT - 1];
        const int tL1 = sh_tok[1][TT - 1];

        float ii0 = sigmoid_fast(g_xprojB[tL0][l]);
        float gg0 = tanh_fast  (g_xprojB[tL0][2 * UU + l]);
        float oo0 = sigmoid_fast(g_xprojB[tL0][3 * UU + l]);
        float hb0 = sh_mask[tL0] ? oo0 * tanh_fast(ii0 * gg0) : 0.f;

        float ii1 = sigmoid_fast(g_xprojB[tL1][l]);
        float gg1 = tanh_fast  (g_xprojB[tL1][2 * UU + l]);
        float oo1 = sigmoid_fast(g_xprojB[tL1][3 * UU + l]);
        float hb1 = sh_mask[tL1] ? oo1 * tanh_fast(ii1 * gg1) : 0.f;

        float ct0 = sh_h[0][0][l] * Wd[l] + hb0 * Wd[UU + l];
        float ct1 = sh_h[1][0][l] * Wd[l] + hb1 * Wd[UU + l];
        #pragma unroll
        for (int off = 16; off > 0; off >>= 1) {
            ct0 += __shfl_down_sync(0xffffffffu, ct0, off);
            ct1 += __shfl_down_sync(0xffffffffu, ct1, off);
        }
        if (lane == 0) {
            sh_red[0][l >> 5] = ct0;    // warps 0,1 hold l<64
            sh_red[1][l >> 5] = ct1;
        }
    }
    __syncthreads();
    if (l == 0) {
        out[b0] = sh_red[0][0] + sh_red[0][1] + bd[0];
        out[b1] = sh_red[1][0] + sh_red[1][1] + bd[0];
    }
}

// Input order (metadata): tokens, emb, Wk_f, Wr_f, b_f, Wk_b, Wr_b, b_b, Wd, bd
extern "C" void kernel_launch(void* const* d_in, const int* in_sizes, int n_in,
                              void* d_out, int out_size) {
    const int*   tokens = (const int*)  d_in[0];
    const float* emb    = (const float*)d_in[1];
    const float* Wk_f   = (const float*)d_in[2];
    const float* Wr_f   = (const float*)d_in[3];
    const float* b_f    = (const float*)d_in[4];
    const float* Wk_b   = (const float*)d_in[5];
    // d_in[6] = Wr_b: unused (backward recurrence collapses to step 1 from h0=0)
    const float* b_b    = (const float*)d_in[7];
    const float* Wd     = (const float*)d_in[8];
    const float* bd     = (const float*)d_in[9];
    float*       out    = (float*)d_out;

    precompute_kernel<<<VV, GG>>>(emb, Wk_f, b_f, Wk_b, b_b);
    lstm_fwd_kernel<<<BB / 2, 128>>>(tokens, Wr_f, Wd, bd, out);
}

// round 16
// speedup vs baseline: 3.1143x; 1.4057x over previous
#include <cuda_runtime.h>

// Problem constants
#define BB 256
#define TT 1024
#define VV 6
#define DD 64
#define UU 64
#define GG 256   // 4*U gate columns

// Precomputed per-vocab tables (V=6).
// Forward table PERMUTED for the 2-col/thread mapping: thread l (u=l>>1,
// p=l&1) owns cols {p*64+u, 128+p*64+u} and reads slots {2l, 2l+1} as LDS.64.
// Original col g (gi=g>>6, u=g&63) -> slot 4u + 2*(gi&1) + (gi>>1).
__device__ float g_xprojF[VV][GG];
__device__ float g_xprojB[VV][GG];   // unpermuted (epilogue indexes by gate)
__device__ int   g_maskv[VV];

// Precise activations (epilogue + precompute only).
__device__ __forceinline__ float sigmoid_fast(float x) {
    return __fdividef(1.f, 1.f + __expf(-x));
}
__device__ __forceinline__ float tanh_fast(float x) {
    return 2.f * __fdividef(1.f, 1.f + __expf(-2.f * x)) - 1.f;
}

// Hot-loop activations via MUFU.TANH (tanh.approx.f32, sm_75+):
// tanh: 1 MUFU (lat~16). sigmoid(x) = 0.5 + 0.5*tanh(0.5x): FMUL+MUFU+FFMA.
__device__ __forceinline__ float tanh_h(float x) {
    float r;
    asm("tanh.approx.f32 %0, %1;" : "=f"(r) : "f"(x));
    return r;
}
__device__ __forceinline__ float sigmoid_h(float x) {
    return fmaf(tanh_h(0.5f * x), 0.5f, 0.5f);
}

__device__ __forceinline__ unsigned long long pack2(float lo, float hi) {
    unsigned long long r;
    asm("mov.b64 %0, {%1, %2};" : "=l"(r) : "f"(lo), "f"(hi));
    return r;
}
__device__ __forceinline__ void unpack2(unsigned long long v, float& lo, float& hi) {
    asm("mov.b64 {%0, %1}, %2;" : "=f"(lo), "=f"(hi) : "l"(v));
}
// Packed dual-FMA: lanes {lo,hi} independently (sm_10x FFMA2 path)
#define FMA2(d, a, b, c) \
    asm("fma.rn.f32x2 %0, %1, %2, %3;" : "=l"(d) : "l"(a), "l"(b), "l"(c))
#define ADD2(d, a, b) \
    asm("add.rn.f32x2 %0, %1, %2;" : "=l"(d) : "l"(a), "l"(b))

__global__ void precompute_kernel(const float* __restrict__ emb,
                                  const float* __restrict__ Wk_f,
                                  const float* __restrict__ b_f,
                                  const float* __restrict__ Wk_b,
                                  const float* __restrict__ b_b) {
    int v = blockIdx.x;
    int g = threadIdx.x;          // original gate column
    float sf = 0.f, sb = 0.f;
    #pragma unroll 8
    for (int k = 0; k < DD; k++) {
        float e = emb[v * DD + k];
        sf = fmaf(e, Wk_f[k * GG + g], sf);
        sb = fmaf(e, Wk_b[k * GG + g], sb);
    }
    int u = g & 63, gi = g >> 6;
    int slot = 4 * u + 2 * (gi & 1) + (gi >> 1);
    g_xprojF[v][slot] = sf + b_f[g];
    g_xprojB[v][g]    = sb + b_b[g];
    if (g == 0) {
        int m = 0;
        for (int k = 0; k < DD; k++) m |= (emb[v * DD + k] != 0.f);
        g_maskv[v] = m;
    }
}

// FUSED step: both batches advance one time-step in ONE statement-interleaved
// instruction stream (R12 structure — proven champion). Activations now on
// the MUFU.TANH path: 6 MUFU/step (was ~12) and tail chains ~24 cyc (was ~44).
// Gate select is branch-free: aB = fmaf(tanh(kB*z), sB, oB) where
// p==0 (g-gate): kB=1,sB=1,oB=0 ; p==1 (o-gate): kB=0.5,sB=0.5,oB=0.5.
__device__ __forceinline__ void lstm_step2(
    const float* __restrict__ hr0, float* __restrict__ hw0,
    const float* __restrict__ hr1, float* __restrict__ hw1,
    const unsigned long long* __restrict__ wA,
    const unsigned long long* __restrict__ wB,
    float2 sd0, float2 sd1, int m0, int m1, int p, int u,
    float kB, float sB, float oB,
    float& c0, float& hp0, float& c1, float& hp1)
{
    // 8 accumulators: [batch][col][chain]; seeds folded into chain 0.
    unsigned long long A00 = pack2(sd0.x, 0.f), A01 = 0ull;  // b0 colA (i/f)
    unsigned long long B00 = pack2(sd0.y, 0.f), B01 = 0ull;  // b0 colB (g/o)
    unsigned long long A10 = pack2(sd1.x, 0.f), A11 = 0ull;  // b1 colA
    unsigned long long B10 = pack2(sd1.y, 0.f), B11 = 0ull;  // b1 colB
    const ulonglong2* __restrict__ h0p = (const ulonglong2*)hr0;
    const ulonglong2* __restrict__ h1p = (const ulonglong2*)hr1;
    #pragma unroll
    for (int i = 0; i < 16; i += 2) {
        ulonglong2 x0 = h0p[i];       // b0 h k-pairs {2i, 2i+1}
        ulonglong2 x1 = h1p[i];       // b1
        ulonglong2 y0 = h0p[i + 1];   // b0 h k-pairs {2i+2, 2i+3}
        ulonglong2 y1 = h1p[i + 1];   // b1
        FMA2(A00, x0.x, wA[2 * i + 0], A00);
        FMA2(A10, x1.x, wA[2 * i + 0], A10);
        FMA2(B00, x0.x, wB[2 * i + 0], B00);
        FMA2(B10, x1.x, wB[2 * i + 0], B10);
        FMA2(A01, x0.y, wA[2 * i + 1], A01);
        FMA2(A11, x1.y, wA[2 * i + 1], A11);
        FMA2(B01, x0.y, wB[2 * i + 1], B01);
        FMA2(B11, x1.y, wB[2 * i + 1], B11);
        FMA2(A00, y0.x, wA[2 * i + 2], A00);
        FMA2(A10, y1.x, wA[2 * i + 2], A10);
        FMA2(B00, y0.x, wB[2 * i + 2], B00);
        FMA2(B10, y1.x, wB[2 * i + 2], B10);
        FMA2(A01, y0.y, wA[2 * i + 3], A01);
        FMA2(A11, y1.y, wA[2 * i + 3], A11);
        FMA2(B01, y0.y, wB[2 * i + 3], B01);
        FMA2(B11, y1.y, wB[2 * i + 3], B11);
    }
    ADD2(A00, A00, A01);
    ADD2(A10, A10, A11);
    ADD2(B00, B00, B01);
    ADD2(B10, B10, B11);
    float lo, hi, zA0, zB0, zA1, zB1;
    unpack2(A00, lo, hi); zA0 = lo + hi;   // b0: i or f
    unpack2(A10, lo, hi); zA1 = lo + hi;   // b1
    unpack2(B00, lo, hi); zB0 = lo + hi;   // b0: g or o
    unpack2(B10, lo, hi); zB1 = lo + hi;   // b1
    // MUFU.TANH activations, interleaved across batches.
    float aA0 = sigmoid_h(zA0);
    float aA1 = sigmoid_h(zA1);
    float aB0 = fmaf(tanh_h(kB * zB0), sB, oB);
    float aB1 = fmaf(tanh_h(kB * zB1), sB, oB);
    float ig0 = __shfl_xor_sync(0xffffffffu, aA0 * aB0, 1);  // A->B: i*g
    float ig1 = __shfl_xor_sync(0xffffffffu, aA1 * aB1, 1);
    if (p == 1) {
        float cn0 = fmaf(aA0, c0, ig0);      // f*c + i*g
        float cn1 = fmaf(aA1, c1, ig1);
        float hn0 = aB0 * tanh_h(cn0);       // o * tanh(c)
        float hn1 = aB1 * tanh_h(cn1);
        c0  = m0 ? cn0 : c0;
        c1  = m1 ? cn1 : c1;
        hp0 = m0 ? hn0 : hp0;
        hp1 = m1 ? hn1 : hp1;
        hw0[u] = hp0;
        hw1[u] = hp1;
    }
}

// Grid 128 CTAs x 128 threads: 1 CTA/SM (single uniform wave), 4 warps/SM =
// ONE warp per SMSP. Each thread runs its 2 gate columns for BOTH of the
// CTA's batches inside one fused, statement-interleaved stream (weights
// shared). One __syncthreads per time-step covers both batches.
__global__ void __launch_bounds__(128, 1)
lstm_fwd_kernel(const int* __restrict__ tokens,
                const float* __restrict__ Wr_f,
                const float* __restrict__ Wd,
                const float* __restrict__ bd,
                float* __restrict__ out) {
    __shared__ float sh_xF[VV * GG];                 // 6 KB (permuted)
    __shared__ int   sh_tok[2][TT + 2];              // pad for prefetch
    __shared__ __align__(16) float sh_h[2][2][UU];   // [batch][parity][unit]
    __shared__ int   sh_mask[VV];
    __shared__ float sh_red[2][2];

    const int l    = threadIdx.x;        // 0..127
    const int b0   = blockIdx.x * 2;
    const int b1   = b0 + 1;
    const int u    = l >> 1;
    const int p    = l & 1;              // 0 = A{i,g}, 1 = B{f,o}
    const int colA = p * UU + u;         // i or f
    const int colB = 2 * UU + p * UU + u;// g or o
    const int lane = l & 31;
    // Branch-free gate-B activation constants (see lstm_step2).
    const float kB = (p == 0) ? 1.0f : 0.5f;
    const float sB = (p == 0) ? 1.0f : 0.5f;
    const float oB = (p == 0) ? 0.0f : 0.5f;

    // Recurrent weight columns as k-pairs (register-resident, shared by both batches).
    unsigned long long wA[32], wB[32];
    #pragma unroll
    for (int j = 0; j < 32; j++) {
        wA[j] = pack2(Wr_f[(2 * j) * GG + colA], Wr_f[(2 * j + 1) * GG + colA]);
        wB[j] = pack2(Wr_f[(2 * j) * GG + colB], Wr_f[(2 * j + 1) * GG + colB]);
    }

    // Stage tokens (both batches) and tables.
    for (int i = l; i < TT; i += 128) {
        sh_tok[0][i] = tokens[b0 * TT + i];
        sh_tok[1][i] = tokens[b1 * TT + i];
    }
    if (l == 0) { sh_tok[0][TT] = 0; sh_tok[0][TT + 1] = 0;
                  sh_tok[1][TT] = 0; sh_tok[1][TT + 1] = 0; }
    for (int i = l; i < VV * GG; i += 128) sh_xF[i] = (&g_xprojF[0][0])[i];
    if (l < VV) sh_mask[l] = g_maskv[l];
    if (l < UU) {
        sh_h[0][0][l] = 0.f; sh_h[0][1][l] = 0.f;
        sh_h[1][0][l] = 0.f; sh_h[1][1][l] = 0.f;
    }
    __syncthreads();

    float c0 = 0.f, hp0 = 0.f;   // batch0 cell/hidden state (B threads)
    float c1 = 0.f, hp1 = 0.f;   // batch1

    // First-step prefetch (tables are init-constant).
    int    tok0 = sh_tok[0][0];
    int    tok1 = sh_tok[1][0];
    float2 sd0  = *(const float2*)&sh_xF[tok0 * GG + 2 * l];
    float2 sd1  = *(const float2*)&sh_xF[tok1 * GG + 2 * l];
    int    m0   = sh_mask[tok0];
    int    m1   = sh_mask[tok1];

    float* __restrict__ h0A = sh_h[0][0];
    float* __restrict__ h0B = sh_h[0][1];
    float* __restrict__ h1A = sh_h[1][0];
    float* __restrict__ h1B = sh_h[1][1];

    for (int s = 0; s < TT; s += 2) {
        // --- even step: read parity0, write parity1 (both batches, fused) ---
        lstm_step2(h0A, h0B, h1A, h1B, wA, wB, sd0, sd1, m0, m1, p, u,
                   kB, sB, oB, c0, hp0, c1, hp1);
        tok0 = sh_tok[0][s + 1];
        tok1 = sh_tok[1][s + 1];
        sd0  = *(const float2*)&sh_xF[tok0 * GG + 2 * l];
        sd1  = *(const float2*)&sh_xF[tok1 * GG + 2 * l];
        m0   = sh_mask[tok0];
        m1   = sh_mask[tok1];
        __syncthreads();
        // --- odd step: read parity1, write parity0 ---
        lstm_step2(h0B, h0A, h1B, h1A, wA, wB, sd0, sd1, m0, m1, p, u,
                   kB, sB, oB, c0, hp0, c1, hp1);
        tok0 = sh_tok[0][s + 2];
        tok1 = sh_tok[1][s + 2];
        sd0  = *(const float2*)&sh_xF[tok0 * GG + 2 * l];
        sd1  = *(const float2*)&sh_xF[tok1 * GG + 2 * l];
        m0   = sh_mask[tok0];
        m1   = sh_mask[tok1];
        __syncthreads();
    }

    // Final forward h is in parity 0 (step 1023 wrote it).
    // Backward direction = its first step only (h0=c0=0): z = xprojB(x[T-1]),
    // c = i*g, h_b = o*tanh(c), masked -> 0. Precise math here (runs once).
    if (l < UU) {
        const int tL0 = sh_tok[0][TT - 1];
        const int tL1 = sh_tok[1][TT - 1];

        float ii0 = sigmoid_fast(g_xprojB[tL0][l]);
        float gg0 = tanh_fast  (g_xprojB[tL0][2 * UU + l]);
        float oo0 = sigmoid_fast(g_xprojB[tL0][3 * UU + l]);
        float hb0 = sh_mask[tL0] ? oo0 * tanh_fast(ii0 * gg0) : 0.f;

        float ii1 = sigmoid_fast(g_xprojB[tL1][l]);
        float gg1 = tanh_fast  (g_xprojB[tL1][2 * UU + l]);
        float oo1 = sigmoid_fast(g_xprojB[tL1][3 * UU + l]);
        float hb1 = sh_mask[tL1] ? oo1 * tanh_fast(ii1 * gg1) : 0.f;

        float ct0 = sh_h[0][0][l] * Wd[l] + hb0 * Wd[UU + l];
        float ct1 = sh_h[1][0][l] * Wd[l] + hb1 * Wd[UU + l];
        #pragma unroll
        for (int off = 16; off > 0; off >>= 1) {
            ct0 += __shfl_down_sync(0xffffffffu, ct0, off);
            ct1 += __shfl_down_sync(0xffffffffu, ct1, off);
        }
        if (lane == 0) {
            sh_red[0][l >> 5] = ct0;    // warps 0,1 hold l<64
            sh_red[1][l >> 5] = ct1;
        }
    }
    __syncthreads();
    if (l == 0) {
        out[b0] = sh_red[0][0] + sh_red[0][1] + bd[0];
        out[b1] = sh_red[1][0] + sh_red[1][1] + bd[0];
    }
}

// Input order (metadata): tokens, emb, Wk_f, Wr_f, b_f, Wk_b, Wr_b, b_b, Wd, bd
extern "C" void kernel_launch(void* const* d_in, const int* in_sizes, int n_in,
                              void* d_out, int out_size) {
    const int*   tokens = (const int*)  d_in[0];
    const float* emb    = (const float*)d_in[1];
    const float* Wk_f   = (const float*)d_in[2];
    const float* Wr_f   = (const float*)d_in[3];
    const float* b_f    = (const float*)d_in[4];
    const float* Wk_b   = (const float*)d_in[5];
    // d_in[6] = Wr_b: unused (backward recurrence collapses to step 1 from h0=0)
    const float* b_b    = (const float*)d_in[7];
    const float* Wd     = (const float*)d_in[8];
    const float* bd     = (const float*)d_in[9];
    float*       out    = (float*)d_out;

    precompute_kernel<<<VV, GG>>>(emb, Wk_f, b_f, Wk_b, b_b);
    lstm_fwd_kernel<<<BB / 2, 128>>>(tokens, Wr_f, Wd, bd, out);
}

// round 17
// speedup vs baseline: 3.4085x; 1.0944x over previous
#include <cuda_runtime.h>

// Problem constants
#define BB 256
#define TT 1024
#define VV 6
#define DD 64
#define UU 64
#define GG 256   // 4*U gate columns

// Precomputed per-vocab tables (V=6).
// Forward table PERMUTED for the 2-col/thread mapping: thread l (u=l>>1,
// p=l&1) owns cols {p*64+u, 128+p*64+u} and reads slots {2l, 2l+1} as LDS.64.
// Original col g (gi=g>>6, u=g&63) -> slot 4u + 2*(gi&1) + (gi>>1).
// SIGMOID PRE-SCALE: slots for sigmoid gates (i, f, o) hold 0.5*(xproj+b),
// so the hot loop computes sigma(z) = fmaf(tanh(z'), 0.5, 0.5) with no FMUL.
// (x0.5 is a power of two -> bit-exact.)
__device__ float g_xprojF[VV][GG];
__device__ float g_xprojB[VV][GG];   // unpermuted, UNSCALED (epilogue)
__device__ int   g_maskv[VV];

// Precise activations (epilogue + precompute only).
__device__ __forceinline__ float sigmoid_fast(float x) {
    return __fdividef(1.f, 1.f + __expf(-x));
}
__device__ __forceinline__ float tanh_fast(float x) {
    return 2.f * __fdividef(1.f, 1.f + __expf(-2.f * x)) - 1.f;
}

// Hot-loop tanh via MUFU.TANH (tanh.approx.f32, sm_75+).
__device__ __forceinline__ float tanh_h(float x) {
    float r;
    asm("tanh.approx.f32 %0, %1;" : "=f"(r) : "f"(x));
    return r;
}

__device__ __forceinline__ unsigned long long pack2(float lo, float hi) {
    unsigned long long r;
    asm("mov.b64 %0, {%1, %2};" : "=l"(r) : "f"(lo), "f"(hi));
    return r;
}
__device__ __forceinline__ void unpack2(unsigned long long v, float& lo, float& hi) {
    asm("mov.b64 {%0, %1}, %2;" : "=f"(lo), "=f"(hi) : "l"(v));
}
// Packed dual-FMA: lanes {lo,hi} independently (sm_10x FFMA2 path)
#define FMA2(d, a, b, c) \
    asm("fma.rn.f32x2 %0, %1, %2, %3;" : "=l"(d) : "l"(a), "l"(b), "l"(c))

__global__ void precompute_kernel(const float* __restrict__ emb,
                                  const float* __restrict__ Wk_f,
                                  const float* __restrict__ b_f,
                                  const float* __restrict__ Wk_b,
                                  const float* __restrict__ b_b) {
    int v = blockIdx.x;
    int g = threadIdx.x;          // original gate column
    float sf = 0.f, sb = 0.f;
    #pragma unroll 8
    for (int k = 0; k < DD; k++) {
        float e = emb[v * DD + k];
        sf = fmaf(e, Wk_f[k * GG + g], sf);
        sb = fmaf(e, Wk_b[k * GG + g], sb);
    }
    int u = g & 63, gi = g >> 6;
    int slot = 4 * u + 2 * (gi & 1) + (gi >> 1);
    // Sigmoid gates (i: gi=0, f: gi=1, o: gi=3) pre-scaled by 0.5 (exact).
    float scale = (gi == 2) ? 1.0f : 0.5f;
    g_xprojF[v][slot] = (sf + b_f[g]) * scale;
    g_xprojB[v][g]    = sb + b_b[g];
    if (g == 0) {
        int m = 0;
        for (int k = 0; k < DD; k++) m |= (emb[v * DD + k] != 0.f);
        g_maskv[v] = m;
    }
}

// FUSED step: both batches advance one time-step in ONE statement-interleaved
// instruction stream (proven champion structure). Single accumulator chain
// per col per batch (depth is immaterial — measured R15); sigmoid 0.5-scales
// folded into weights/seeds, so activations are:
//   aA = fmaf(tanh(zA), 0.5, 0.5)            (i or f, pre-scaled z)
//   aB = fmaf(tanh(zB), sB, oB)              (g: sB=1,oB=0 ; o: sB=.5,oB=.5)
__device__ __forceinline__ void lstm_step2(
    const float* __restrict__ hr0, float* __restrict__ hw0,
    const float* __restrict__ hr1, float* __restrict__ hw1,
    const unsigned long long* __restrict__ wA,
    const unsigned long long* __restrict__ wB,
    float2 sd0, float2 sd1, int m0, int m1, int p, int u,
    float sB, float oB,
    float& c0, float& hp0, float& c1, float& hp1)
{
    // 4 accumulators: [batch][col]; seeds folded into the lo lane.
    unsigned long long A0 = pack2(sd0.x, 0.f);   // b0 colA (i/f, pre-scaled)
    unsigned long long B0 = pack2(sd0.y, 0.f);   // b0 colB (g/o)
    unsigned long long A1 = pack2(sd1.x, 0.f);   // b1 colA
    unsigned long long B1 = pack2(sd1.y, 0.f);   // b1 colB
    const ulonglong2* __restrict__ h0p = (const ulonglong2*)hr0;
    const ulonglong2* __restrict__ h1p = (const ulonglong2*)hr1;
    #pragma unroll
    for (int i = 0; i < 16; i += 2) {
        ulonglong2 x0 = h0p[i];       // b0 h k-pairs {2i, 2i+1}
        ulonglong2 x1 = h1p[i];       // b1
        ulonglong2 y0 = h0p[i + 1];   // b0 h k-pairs {2i+2, 2i+3}
        ulonglong2 y1 = h1p[i + 1];   // b1
        FMA2(A0, x0.x, wA[2 * i + 0], A0);
        FMA2(A1, x1.x, wA[2 * i + 0], A1);
        FMA2(B0, x0.x, wB[2 * i + 0], B0);
        FMA2(B1, x1.x, wB[2 * i + 0], B1);
        FMA2(A0, x0.y, wA[2 * i + 1], A0);
        FMA2(A1, x1.y, wA[2 * i + 1], A1);
        FMA2(B0, x0.y, wB[2 * i + 1], B0);
        FMA2(B1, x1.y, wB[2 * i + 1], B1);
        FMA2(A0, y0.x, wA[2 * i + 2], A0);
        FMA2(A1, y1.x, wA[2 * i + 2], A1);
        FMA2(B0, y0.x, wB[2 * i + 2], B0);
        FMA2(B1, y1.x, wB[2 * i + 2], B1);
        FMA2(A0, y0.y, wA[2 * i + 3], A0);
        FMA2(A1, y1.y, wA[2 * i + 3], A1);
        FMA2(B0, y0.y, wB[2 * i + 3], B0);
        FMA2(B1, y1.y, wB[2 * i + 3], B1);
    }
    float lo, hi, zA0, zB0, zA1, zB1;
    unpack2(A0, lo, hi); zA0 = lo + hi;   // b0: i or f (pre-scaled by 0.5)
    unpack2(A1, lo, hi); zA1 = lo + hi;   // b1
    unpack2(B0, lo, hi); zB0 = lo + hi;   // b0: g or o (o pre-scaled)
    unpack2(B1, lo, hi); zB1 = lo + hi;   // b1
    // MUFU.TANH activations, interleaved across batches; no pre-FMULs.
    float aA0 = fmaf(tanh_h(zA0), 0.5f, 0.5f);
    float aA1 = fmaf(tanh_h(zA1), 0.5f, 0.5f);
    float aB0 = fmaf(tanh_h(zB0), sB, oB);
    float aB1 = fmaf(tanh_h(zB1), sB, oB);
    float ig0 = __shfl_xor_sync(0xffffffffu, aA0 * aB0, 1);  // A->B: i*g
    float ig1 = __shfl_xor_sync(0xffffffffu, aA1 * aB1, 1);
    if (p == 1) {
        float cn0 = fmaf(aA0, c0, ig0);      // f*c + i*g
        float cn1 = fmaf(aA1, c1, ig1);
        float hn0 = aB0 * tanh_h(cn0);       // o * tanh(c)
        float hn1 = aB1 * tanh_h(cn1);
        c0  = m0 ? cn0 : c0;
        c1  = m1 ? cn1 : c1;
        hp0 = m0 ? hn0 : hp0;
        hp1 = m1 ? hn1 : hp1;
        hw0[u] = hp0;
        hw1[u] = hp1;
    }
}

// Grid 128 CTAs x 128 threads: 1 CTA/SM (single uniform wave), 4 warps/SM =
// ONE warp per SMSP. Each thread runs its 2 gate columns for BOTH of the
// CTA's batches inside one fused, statement-interleaved stream (weights
// shared). One __syncthreads per time-step covers both batches.
__global__ void __launch_bounds__(128, 1)
lstm_fwd_kernel(const int* __restrict__ tokens,
                const float* __restrict__ Wr_f,
                const float* __restrict__ Wd,
                const float* __restrict__ bd,
                float* __restrict__ out) {
    __shared__ float sh_xF[VV * GG];                 // 6 KB (permuted, scaled)
    __shared__ int   sh_tok[2][TT + 2];              // pad for prefetch
    __shared__ __align__(16) float sh_h[2][2][UU];   // [batch][parity][unit]
    __shared__ int   sh_mask[VV];
    __shared__ float sh_red[2][2];

    const int l    = threadIdx.x;        // 0..127
    const int b0   = blockIdx.x * 2;
    const int b1   = b0 + 1;
    const int u    = l >> 1;
    const int p    = l & 1;              // 0 = A{i,g}, 1 = B{f,o}
    const int colA = p * UU + u;         // i or f
    const int colB = 2 * UU + p * UU + u;// g or o
    const int lane = l & 31;
    // Branch-free gate-B activation constants.
    const float sB = (p == 0) ? 1.0f : 0.5f;
    const float oB = (p == 0) ? 0.0f : 0.5f;
    // Weight pre-scales: colA (i/f) always sigmoid -> 0.5 ; colB sigmoid only
    // for p==1 (o-gate).
    const float wsA = 0.5f;
    const float wsB = (p == 0) ? 1.0f : 0.5f;

    // Recurrent weight columns as k-pairs (register-resident, shared by both
    // batches), pre-scaled for the folded sigmoid (exact x0.5).
    unsigned long long wA[32], wB[32];
    #pragma unroll
    for (int j = 0; j < 32; j++) {
        wA[j] = pack2(wsA * Wr_f[(2 * j) * GG + colA],
                      wsA * Wr_f[(2 * j + 1) * GG + colA]);
        wB[j] = pack2(wsB * Wr_f[(2 * j) * GG + colB],
                      wsB * Wr_f[(2 * j + 1) * GG + colB]);
    }

    // Stage tokens (both batches) and tables.
    for (int i = l; i < TT; i += 128) {
        sh_tok[0][i] = tokens[b0 * TT + i];
        sh_tok[1][i] = tokens[b1 * TT + i];
    }
    if (l == 0) { sh_tok[0][TT] = 0; sh_tok[0][TT + 1] = 0;
                  sh_tok[1][TT] = 0; sh_tok[1][TT + 1] = 0; }
    for (int i = l; i < VV * GG; i += 128) sh_xF[i] = (&g_xprojF[0][0])[i];
    if (l < VV) sh_mask[l] = g_maskv[l];
    if (l < UU) {
        sh_h[0][0][l] = 0.f; sh_h[0][1][l] = 0.f;
        sh_h[1][0][l] = 0.f; sh_h[1][1][l] = 0.f;
    }
    __syncthreads();

    float c0 = 0.f, hp0 = 0.f;   // batch0 cell/hidden state (B threads)
    float c1 = 0.f, hp1 = 0.f;   // batch1

    // First-step prefetch (tables are init-constant).
    int    tok0 = sh_tok[0][0];
    int    tok1 = sh_tok[1][0];
    float2 sd0  = *(const float2*)&sh_xF[tok0 * GG + 2 * l];
    float2 sd1  = *(const float2*)&sh_xF[tok1 * GG + 2 * l];
    int    m0   = sh_mask[tok0];
    int    m1   = sh_mask[tok1];

    float* __restrict__ h0A = sh_h[0][0];
    float* __restrict__ h0B = sh_h[0][1];
    float* __restrict__ h1A = sh_h[1][0];
    float* __restrict__ h1B = sh_h[1][1];

    for (int s = 0; s < TT; s += 2) {
        // --- even step: read parity0, write parity1 (both batches, fused) ---
        lstm_step2(h0A, h0B, h1A, h1B, wA, wB, sd0, sd1, m0, m1, p, u,
                   sB, oB, c0, hp0, c1, hp1);
        tok0 = sh_tok[0][s + 1];
        tok1 = sh_tok[1][s + 1];
        sd0  = *(const float2*)&sh_xF[tok0 * GG + 2 * l];
        sd1  = *(const float2*)&sh_xF[tok1 * GG + 2 * l];
        m0   = sh_mask[tok0];
        m1   = sh_mask[tok1];
        __syncthreads();
        // --- odd step: read parity1, write parity0 ---
        lstm_step2(h0B, h0A, h1B, h1A, wA, wB, sd0, sd1, m0, m1, p, u,
                   sB, oB, c0, hp0, c1, hp1);
        tok0 = sh_tok[0][s + 2];
        tok1 = sh_tok[1][s + 2];
        sd0  = *(const float2*)&sh_xF[tok0 * GG + 2 * l];
        sd1  = *(const float2*)&sh_xF[tok1 * GG + 2 * l];
        m0   = sh_mask[tok0];
        m1   = sh_mask[tok1];
        __syncthreads();
    }

    // Final forward h is in parity 0 (step 1023 wrote it).
    // Backward direction = its first step only (h0=c0=0): z = xprojB(x[T-1]),
    // c = i*g, h_b = o*tanh(c), masked -> 0. Precise math here (runs once,
    // on the UNSCALED backward table).
    if (l < UU) {
        const int tL0 = sh_tok[0][TT - 1];
        const int tL1 = sh_tok[1][TT - 1];

        float ii0 = sigmoid_fast(g_xprojB[tL0][l]);
        float gg0 = tanh_fast  (g_xprojB[tL0][2 * UU + l]);
        float oo0 = sigmoid_fast(g_xprojB[tL0][3 * UU + l]);
        float hb0 = sh_mask[tL0] ? oo0 * tanh_fast(ii0 * gg0) : 0.f;

        float ii1 = sigmoid_fast(g_xprojB[tL1][l]);
        float gg1 = tanh_fast  (g_xprojB[tL1][2 * UU + l]);
        float oo1 = sigmoid_fast(g_xprojB[tL1][3 * UU + l]);
        float hb1 = sh_mask[tL1] ? oo1 * tanh_fast(ii1 * gg1) : 0.f;

        float ct0 = sh_h[0][0][l] * Wd[l] + hb0 * Wd[UU + l];
        float ct1 = sh_h[1][0][l] * Wd[l] + hb1 * Wd[UU + l];
        #pragma unroll
        for (int off = 16; off > 0; off >>= 1) {
            ct0 += __shfl_down_sync(0xffffffffu, ct0, off);
            ct1 += __shfl_down_sync(0xffffffffu, ct1, off);
        }
        if (lane == 0) {
            sh_red[0][l >> 5] = ct0;    // warps 0,1 hold l<64
            sh_red[1][l >> 5] = ct1;
        }
    }
    __syncthreads();
    if (l == 0) {
        out[b0] = sh_red[0][0] + sh_red[0][1] + bd[0];
        out[b1] = sh_red[1][0] + sh_red[1][1] + bd[0];
    }
}

// Input order (metadata): tokens, emb, Wk_f, Wr_f, b_f, Wk_b, Wr_b, b_b, Wd, bd
extern "C" void kernel_launch(void* const* d_in, const int* in_sizes, int n_in,
                              void* d_out, int out_size) {
    const int*   tokens = (const int*)  d_in[0];
    const float* emb    = (const float*)d_in[1];
    const float* Wk_f   = (const float*)d_in[2];
    const float* Wr_f   = (const float*)d_in[3];
    const float* b_f    = (const float*)d_in[4];
    const float* Wk_b   = (const float*)d_in[5];
    // d_in[6] = Wr_b: unused (backward recurrence collapses to step 1 from h0=0)
    const float* b_b    = (const float*)d_in[7];
    const float* Wd     = (const float*)d_in[8];
    const float* bd     = (const float*)d_in[9];
    float*       out    = (float*)d_out;

    precompute_kernel<<<VV, GG>>>(emb, Wk_f, b_f, Wk_b, b_b);
    lstm_fwd_kernel<<<BB / 2, 128>>>(tokens, Wr_f, Wd, bd, out);
}